// round 17
// baseline (speedup 1.0000x reference)
#include <cuda_runtime.h>
#include <cuda_fp16.h>
#include <cstdint>
#include <cstddef>

// ---------------------------------------------------------------------------
// NeuralODE Dopri5. One kernel per MLP EVAL (3 GEMM phases), 240 launches.
// Cluster (8,1,1): each cluster owns a 64-row block; layer boundaries are
// threadfence + barrier.cluster instead of kernel boundaries.
// GEMM phase = R15 core: mma.sync m16n8k16 FP16 (2xFP16 split, 3 products,
// fp32 accum), all operands fp16 hi/lo in gmem, 4-stage cp.async pipeline,
// wait_group 2, ldmatrix, compile-time K. RK combine fused in phase-3 epi.
// ---------------------------------------------------------------------------

#define BB 1024
#define DD 256
#define HH 512
#define N_STEPS 40
#define HSTEP 0.25f

__device__ float  g_y [BB * DD];
__device__ float  g_k [6][BB * DD];
__device__ __half g_yh  [BB * DD], g_yl  [BB * DD];
__device__ __half g_cmh [BB * DD], g_cml [BB * DD];
__device__ __half g_h1h [BB * HH], g_h1l [BB * HH];
__device__ __half g_h2h [BB * HH], g_h2l [BB * HH];
__device__ __half g_W1hi[HH * DD], g_W1lo[HH * DD];
__device__ __half g_W2hi[HH * HH], g_W2lo[HH * HH];
__device__ __half g_W3hi[DD * HH], g_W3lo[DD * HH];

struct Epi {
    const float* yin;
    const float* ks[4];
    float        cks[4];
    int          nks;
    float        cself;
    __half*      auxh;
    __half*      auxl;
    float*       auxfp;
    float*       emit;
    int          t;
};

// ----------------------------- helpers -------------------------------------
__device__ __forceinline__ uint32_t smem_u32(const void* p) {
    uint32_t a;
    asm("{ .reg .u64 t; cvta.to.shared.u64 t, %1; cvt.u32.u64 %0, t; }"
        : "=r"(a) : "l"(p));
    return a;
}
__device__ __forceinline__ uint32_t packh2(__half a, __half b) {
    __half2 t = __halves2half2(a, b);
    return *reinterpret_cast<uint32_t*>(&t);
}
__device__ __forceinline__ void cp16(uint32_t d, const void* s) {
    asm volatile("cp.async.cg.shared.global [%0], [%1], 16;"
                 :: "r"(d), "l"(s) : "memory");
}
__device__ __forceinline__ void cp_commit() {
    asm volatile("cp.async.commit_group;" ::: "memory");
}
__device__ __forceinline__ void cp_wait2() {
    asm volatile("cp.async.wait_group 2;" ::: "memory");
}
__device__ __forceinline__ void cp_wait0() {
    asm volatile("cp.async.wait_group 0;" ::: "memory");
}
__device__ __forceinline__ void cluster_sync_() {
    asm volatile("barrier.cluster.arrive.aligned;" ::: "memory");
    asm volatile("barrier.cluster.wait.aligned;" ::: "memory");
}
__device__ __forceinline__ void ldm4(uint32_t* r, uint32_t addr) {
    asm volatile("ldmatrix.sync.aligned.m8n8.x4.shared.b16 {%0,%1,%2,%3}, [%4];"
                 : "=r"(r[0]), "=r"(r[1]), "=r"(r[2]), "=r"(r[3]) : "r"(addr));
}
__device__ __forceinline__ void mma16(float* d, const uint32_t* a,
                                      uint32_t b0, uint32_t b1) {
    asm volatile(
        "mma.sync.aligned.m16n8k16.row.col.f32.f16.f16.f32 "
        "{%0,%1,%2,%3}, {%4,%5,%6,%7}, {%8,%9}, {%0,%1,%2,%3};"
        : "+f"(d[0]), "+f"(d[1]), "+f"(d[2]), "+f"(d[3])
        : "r"(a[0]), "r"(a[1]), "r"(a[2]), "r"(a[3]), "r"(b0), "r"(b1));
}

// ---------------------------------------------------------------------------
// One GEMM phase (R15 core as a device function).
// 256 threads, warp grid 2(M)x4(N), warp tile (16*MT)x16, CTA tile (32*MT)x64.
// BK=64, S=K/64 fully unrolled, 4-stage cp.async ring, wait_group 2,
// one __syncthreads + one commit per stage. Smem rows 128B, XOR swizzle.
// MODE 0: relu, outputs split fp16 (Chi/Clo).
// MODE 1: fp32 store + fused RK combine (epilogue operands prefetched early).
// ---------------------------------------------------------------------------
template<int K, int MT, int MODE>
__device__ __forceinline__ void gemm_phase(
    const __half* __restrict__ Ahi, const __half* __restrict__ Alo,
    const __half* __restrict__ Whi, const __half* __restrict__ Wlo,
    const float* __restrict__ bias,
    float* __restrict__ C, __half* __restrict__ Chi, __half* __restrict__ Clo,
    const int N, const int m0, const int n0, const uint32_t sb, const Epi& ep)
{
    constexpr int BM  = 32 * MT;
    constexpr int TPR = 256 / BM;
    constexpr int CPT = 8 / TPR;
    constexpr int S   = K / 64;
    constexpr uint32_t AB = (uint32_t)BM * 128;
    constexpr uint32_t WB = 64 * 128;
    constexpr uint32_t WOFFS = 2 * AB;
    constexpr uint32_t STRIDE = 2 * AB + 2 * WB;

    const int tid  = threadIdx.x;
    const int warp = tid >> 5, lane = tid & 31;
    const int wM = warp >> 2, wN = warp & 3;
    const int g = lane >> 2, c = lane & 3;

    const int arw  = tid / TPR;
    const int akc0 = (tid % TPR) * CPT;
    const int wrw  = tid >> 2;
    const int wkc0 = (tid & 3) * 2;
    const __half* aSrcH = Ahi + (size_t)(m0 + arw) * K + akc0 * 8;
    const __half* aSrcL = Alo + (size_t)(m0 + arw) * K + akc0 * 8;
    const __half* wSrcH = Whi + (size_t)(n0 + wrw) * K + wkc0 * 8;
    const __half* wSrcL = Wlo + (size_t)(n0 + wrw) * K + wkc0 * 8;
    const uint32_t aDst0 = (uint32_t)arw * 128;
    const uint32_t wDst0 = WOFFS + (uint32_t)wrw * 128;

    const int quad = lane >> 3, l8 = lane & 7;
    const uint32_t aqs = (uint32_t)(quad >> 1);
    const uint32_t bqs = (uint32_t)(quad & 1);
    uint32_t aoffA[MT];
    #pragma unroll
    for (int i = 0; i < MT; i++)
        aoffA[i] = (uint32_t)(wM * 16 * MT + i * 16 + ((quad & 1) << 3) + l8) * 128;
    const uint32_t boffB = WOFFS
        + (uint32_t)(wN * 16 + ((quad >> 1) << 3) + l8) * 128;

    auto cpStage = [&](int s, int buf) {
        const uint32_t b0 = sb + (uint32_t)buf * STRIDE;
        #pragma unroll
        for (int q = 0; q < CPT; q++) {
            const int kc = akc0 + q;
            const uint32_t d = b0 + aDst0 + (uint32_t)((kc ^ (arw & 7)) << 4);
            cp16(d,      aSrcH + s * 64 + q * 8);
            cp16(d + AB, aSrcL + s * 64 + q * 8);
        }
        #pragma unroll
        for (int q = 0; q < 2; q++) {
            const int kc = wkc0 + q;
            const uint32_t d = b0 + wDst0 + (uint32_t)((kc ^ (wrw & 7)) << 4);
            cp16(d,      wSrcH + s * 64 + q * 8);
            cp16(d + WB, wSrcL + s * 64 + q * 8);
        }
        cp_commit();
    };

    float acc[MT][2][4];
    #pragma unroll
    for (int i = 0; i < MT; i++)
        #pragma unroll
        for (int nt = 0; nt < 2; nt++)
            #pragma unroll
            for (int q = 0; q < 4; q++) acc[i][nt][q] = 0.0f;

    cpStage(0, 0);
    cpStage(1, 1);
    cpStage(2, 2);

    // epilogue operand prefetch (hidden under the mainloop)
    float2 pre_y[MT][2][2];
    float2 pre_k[4][MT][2][2];
    float  bpre[2][2];
    if (MODE == 1) {
        #pragma unroll
        for (int nt = 0; nt < 2; nt++) {
            const int col = n0 + wN * 16 + nt * 8 + 2 * c;
            bpre[nt][0] = bias[col];
            bpre[nt][1] = bias[col + 1];
            #pragma unroll
            for (int i = 0; i < MT; i++) {
                #pragma unroll
                for (int hh = 0; hh < 2; hh++) {
                    const int row = m0 + wM * 16 * MT + i * 16 + g + 8 * hh;
                    const size_t idx = (size_t)row * N + col;
                    pre_y[i][nt][hh] = *(const float2*)(ep.yin + idx);
                    for (int t = 0; t < ep.nks; t++)
                        pre_k[t][i][nt][hh] = *(const float2*)(ep.ks[t] + idx);
                }
            }
        }
    }

    #pragma unroll
    for (int s = 0; s < S; s++) {
        cp_wait2();
        __syncthreads();
        if (s + 3 < S) cpStage(s + 3, (s + 3) & 3);
        else           cp_commit();

        const uint32_t base = sb + (uint32_t)(s & 3) * STRIDE;
        uint32_t ah[2][MT][4], al[2][MT][4], bh[2][4], bl[2][4];

        auto ldfrag = [&](int j, int fb) {
            const uint32_t colA = (uint32_t)(((2 * j + aqs) ^ l8) << 4);
            const uint32_t colB = (uint32_t)(((2 * j + bqs) ^ l8) << 4);
            #pragma unroll
            for (int i = 0; i < MT; i++) {
                ldm4(ah[fb][i], base + aoffA[i] + colA);
                ldm4(al[fb][i], base + AB + aoffA[i] + colA);
            }
            ldm4(bh[fb], base + boffB + colB);
            ldm4(bl[fb], base + WB + boffB + colB);
        };

        ldfrag(0, 0);
        #pragma unroll
        for (int j = 0; j < 4; j++) {
            const int fb = j & 1;
            if (j < 3) ldfrag(j + 1, fb ^ 1);
            #pragma unroll
            for (int i = 0; i < MT; i++) {
                mma16(acc[i][0], ah[fb][i], bh[fb][0], bh[fb][1]);
                mma16(acc[i][1], ah[fb][i], bh[fb][2], bh[fb][3]);
                mma16(acc[i][0], ah[fb][i], bl[fb][0], bl[fb][1]);
                mma16(acc[i][1], ah[fb][i], bl[fb][2], bl[fb][3]);
                mma16(acc[i][0], al[fb][i], bh[fb][0], bh[fb][1]);
                mma16(acc[i][1], al[fb][i], bh[fb][2], bh[fb][3]);
            }
        }
    }

    // ---- epilogue ----
    #pragma unroll
    for (int i = 0; i < MT; i++) {
        #pragma unroll
        for (int nt = 0; nt < 2; nt++) {
            const int col = n0 + wN * 16 + nt * 8 + 2 * c;
            const int row0 = m0 + wM * 16 * MT + i * 16 + g;
            float b0v, b1v;
            if (MODE == 1) { b0v = bpre[nt][0]; b1v = bpre[nt][1]; }
            else           { b0v = bias[col];   b1v = bias[col + 1]; }
            #pragma unroll
            for (int hh = 0; hh < 2; hh++) {
                const int row = row0 + 8 * hh;
                float v0 = acc[i][nt][2 * hh + 0] + b0v;
                float v1 = acc[i][nt][2 * hh + 1] + b1v;
                const size_t idx = (size_t)row * N + col;
                if (MODE == 0) {
                    v0 = fmaxf(v0, 0.0f); v1 = fmaxf(v1, 0.0f);
                    __half h0 = __float2half_rn(v0), h1 = __float2half_rn(v1);
                    *reinterpret_cast<uint32_t*>(Chi + idx) = packh2(h0, h1);
                    *reinterpret_cast<uint32_t*>(Clo + idx) = packh2(
                        __float2half_rn(v0 - __half2float(h0)),
                        __float2half_rn(v1 - __half2float(h1)));
                } else {
                    *(float2*)(C + idx) = make_float2(v0, v1);
                    float a0 = pre_y[i][nt][hh].x + ep.cself * v0;
                    float a1 = pre_y[i][nt][hh].y + ep.cself * v1;
                    for (int t = 0; t < ep.nks; t++) {
                        a0 += ep.cks[t] * pre_k[t][i][nt][hh].x;
                        a1 += ep.cks[t] * pre_k[t][i][nt][hh].y;
                    }
                    __half h0 = __float2half_rn(a0), h1 = __float2half_rn(a1);
                    *reinterpret_cast<uint32_t*>(ep.auxh + idx) = packh2(h0, h1);
                    *reinterpret_cast<uint32_t*>(ep.auxl + idx) = packh2(
                        __float2half_rn(a0 - __half2float(h0)),
                        __float2half_rn(a1 - __half2float(h1)));
                    if (ep.auxfp)
                        *(float2*)(ep.auxfp + idx) = make_float2(a0, a1);
                    if (ep.emit) {
                        const size_t o = (size_t)row * (10 * DD) + (size_t)ep.t * DD + col;
                        *(float2*)(ep.emit + o) = make_float2(a0, a1);
                    }
                }
            }
        }
    }
}

// ---------------------------------------------------------------------------
// One MLP EVAL: 3 GEMM phases inside one kernel, cluster (8,1,1).
// blockIdx.y -> 64-row block; blockIdx.x -> N-slice. The cluster's 8 CTAs
// jointly produce all columns of h1/h2 for their row block, so layer
// boundaries are fence + barrier.cluster (no kernel boundary, no grid tail).
// ---------------------------------------------------------------------------
__global__ __launch_bounds__(256, 1)
void eval_kernel(const __half* __restrict__ Ah, const __half* __restrict__ Al,
                 const float* __restrict__ b1, const float* __restrict__ b2,
                 const float* __restrict__ b3, float* __restrict__ kout, Epi ep)
{
    extern __shared__ float smem[];
    const uint32_t sb = smem_u32(smem);
    const int bx = blockIdx.x;             // 0..7 (cluster-local N slice)
    const int mb = blockIdx.y * 64;        // 64-row block

    Epi edum = {};

    // Phase 1: h1 = relu(A @ W1^T + b1), tile [mb, bx*64], K=256
    gemm_phase<256, 2, 0>(Ah, Al, g_W1hi, g_W1lo, b1,
                          nullptr, g_h1h, g_h1l, HH, mb, bx * 64, sb, edum);
    cp_wait0();
    __threadfence();
    cluster_sync_();

    // Phase 2: h2 = relu(h1 @ W2^T + b2), tile [mb, bx*64], K=512
    gemm_phase<512, 2, 0>(g_h1h, g_h1l, g_W2hi, g_W2lo, b2,
                          nullptr, g_h2h, g_h2l, HH, mb, bx * 64, sb, edum);
    cp_wait0();
    __threadfence();
    cluster_sync_();

    // Phase 3: k = h2 @ W3^T + b3 (+ fused RK combine), tile 32x64:
    // rows mb + (bx>>2)*32, cols (bx&3)*64 — 8 CTAs cover [64 x 256].
    gemm_phase<512, 1, 1>(g_h2h, g_h2l, g_W3hi, g_W3lo, b3,
                          kout, nullptr, nullptr, DD,
                          mb + (bx >> 2) * 32, (bx & 3) * 64, sb, ep);
}

// Split fp32 X into fp16 hi/lo parts
__global__ void wsplit_kernel(const float* __restrict__ X,
                              __half* __restrict__ hi, __half* __restrict__ lo,
                              int n)
{
    int i = blockIdx.x * blockDim.x + threadIdx.x;
    if (i < n) {
        float x = X[i];
        __half h = __float2half_rn(x);
        hi[i] = h;
        lo[i] = __float2half_rn(x - __half2float(h));
    }
}

extern "C" void kernel_launch(void* const* d_in, const int* in_sizes, int n_in,
                              void* d_out, int out_size)
{
    (void)in_sizes; (void)n_in; (void)out_size;
    const float* x0 = (const float*)d_in[0];
    // d_in[1] is T (int32, always 11) — baked into the graph.
    const float* W1 = (const float*)d_in[2];
    const float* b1 = (const float*)d_in[3];
    const float* W2 = (const float*)d_in[4];
    const float* b2 = (const float*)d_in[5];
    const float* W3 = (const float*)d_in[6];
    const float* b3 = (const float*)d_in[7];
    float* out = (float*)d_out;

    float *y, *kbase;
    __half *yh, *yl, *cmh, *cml;
    __half *w1h, *w1l, *w2h, *w2l, *w3h, *w3l;
    cudaGetSymbolAddress((void**)&y,     g_y);
    cudaGetSymbolAddress((void**)&kbase, g_k);
    cudaGetSymbolAddress((void**)&yh,    g_yh);
    cudaGetSymbolAddress((void**)&yl,    g_yl);
    cudaGetSymbolAddress((void**)&cmh,   g_cmh);
    cudaGetSymbolAddress((void**)&cml,   g_cml);
    cudaGetSymbolAddress((void**)&w1h,   g_W1hi);
    cudaGetSymbolAddress((void**)&w1l,   g_W1lo);
    cudaGetSymbolAddress((void**)&w2h,   g_W2hi);
    cudaGetSymbolAddress((void**)&w2l,   g_W2lo);
    cudaGetSymbolAddress((void**)&w3h,   g_W3hi);
    cudaGetSymbolAddress((void**)&w3l,   g_W3lo);
    float* k[6];
    for (int j = 0; j < 6; j++) k[j] = (float*)kbase + (size_t)j * BB * DD;

    // 4 stage buffers of (2*AB + 2*WB) at MT=2 -> 131072 bytes
    const int SMEM = 4 * (2 * 64 * 128 + 2 * 64 * 128);
    cudaFuncSetAttribute((const void*)&eval_kernel,
                         cudaFuncAttributeMaxDynamicSharedMemorySize, SMEM);

    // y = x0[:,0,:]; split to fp16 hi/lo
    cudaMemcpyAsync(y, x0, sizeof(float) * BB * DD, cudaMemcpyDeviceToDevice);
    wsplit_kernel<<<(BB * DD + 255) / 256, 256>>>(x0, yh, yl, BB * DD);
    wsplit_kernel<<<(HH * DD + 255) / 256, 256>>>(W1, w1h, w1l, HH * DD);
    wsplit_kernel<<<(HH * HH + 255) / 256, 256>>>(W2, w2h, w2l, HH * HH);
    wsplit_kernel<<<(DD * HH + 255) / 256, 256>>>(W3, w3h, w3l, DD * HH);

    // Dopri5 tableau
    const double A2[] = {1.0/5.0};
    const double A3[] = {3.0/40.0, 9.0/40.0};
    const double A4[] = {44.0/45.0, -56.0/15.0, 32.0/9.0};
    const double A5[] = {19372.0/6561.0, -25360.0/2187.0, 64448.0/6561.0, -212.0/729.0};
    const double A6[] = {9017.0/3168.0, -355.0/33.0, 46732.0/5247.0, 49.0/176.0, -5103.0/18656.0};
    const double* Arows[5] = {A2, A3, A4, A5, A6};

    // Cluster launch config: grid (8,16), cluster (8,1,1)
    cudaLaunchAttribute attrs[1];
    attrs[0].id = cudaLaunchAttributeClusterDimension;
    attrs[0].val.clusterDim = {8, 1, 1};
    cudaLaunchConfig_t cfg = {};
    cfg.gridDim = dim3(8, 16, 1);
    cfg.blockDim = dim3(256, 1, 1);
    cfg.dynamicSmemBytes = SMEM;
    cfg.stream = 0;
    cfg.attrs = attrs;
    cfg.numAttrs = 1;

    for (int step = 0; step < N_STEPS; step++) {
        for (int s = 0; s < 6; s++) {
            const __half* Ah = (s == 0) ? yh : cmh;
            const __half* Al = (s == 0) ? yl : cml;

            Epi ep = {};
            ep.yin = y;
            if (s < 5) {
                const double* row = Arows[s];
                ep.nks = s;
                for (int j = 0; j < s; j++) {
                    ep.ks[j]  = k[j];
                    ep.cks[j] = (float)((double)HSTEP * row[j]);
                }
                ep.cself = (float)((double)HSTEP * row[s]);
                ep.auxh  = cmh;
                ep.auxl  = cml;
                ep.auxfp = nullptr;
                ep.emit  = nullptr;
                ep.t     = 0;
            } else {
                ep.nks = 4;
                ep.ks[0] = k[0]; ep.cks[0] = (float)((double)HSTEP * (35.0 / 384.0));
                ep.ks[1] = k[2]; ep.cks[1] = (float)((double)HSTEP * (500.0 / 1113.0));
                ep.ks[2] = k[3]; ep.cks[2] = (float)((double)HSTEP * (125.0 / 192.0));
                ep.ks[3] = k[4]; ep.cks[3] = (float)((double)HSTEP * (-2187.0 / 6784.0));
                ep.cself = (float)((double)HSTEP * (11.0 / 84.0));
                ep.auxh  = yh;
                ep.auxl  = yl;
                ep.auxfp = y;
                ep.emit  = ((step & 3) == 3) ? out : nullptr;
                ep.t     = step >> 2;
            }
            cudaLaunchKernelEx(&cfg, eval_kernel, Ah, Al, b1, b2, b3, k[s], ep);
        }
    }
}